// round 13
// baseline (speedup 1.0000x reference)
#include <cuda_runtime.h>

#define MAXN   100000
#define MAXE   3200000
#define IN_DIM 128
#define HID    64
#define G_NUM  256
#define SCAN_B 1024
#define NPG    8          // nodes per 8-lane group in k_gather_pool

typedef unsigned long long u64;
typedef unsigned int u32;

// ---- packed fp32x2 helpers (sm_100+) ----
__device__ __forceinline__ u64 pack2(float lo, float hi) {
    u64 r; asm("mov.b64 %0, {%1, %2};" : "=l"(r) : "f"(lo), "f"(hi)); return r;
}
__device__ __forceinline__ u64 ffma2(u64 a, u64 b, u64 c) {
    u64 d; asm("fma.rn.f32x2 %0, %1, %2, %3;" : "=l"(d) : "l"(a), "l"(b), "l"(c)); return d;
}
__device__ __forceinline__ float2 unpack2(u64 v) {
    float2 f; asm("mov.b64 {%0, %1}, %2;" : "=f"(f.x), "=f"(f.y) : "l"(v)); return f;
}
__device__ __forceinline__ u32 cvt_bf16x2(float lo, float hi) {
    u32 r; asm("cvt.rn.bf16x2.f32 %0, %1, %2;" : "=r"(r) : "f"(hi), "f"(lo)); return r;
}
__device__ __forceinline__ u64 bf2f2(u32 u) {
    u32 lo = u << 16;
    u32 hi = u & 0xFFFF0000u;
    u64 r; asm("mov.b64 %0, {%1, %2};" : "=l"(r) : "r"(lo), "r"(hi)); return r;
}
// ---- cp.async helpers ----
__device__ __forceinline__ void cp16(void* sdst, const void* gsrc) {
    u32 s = (u32)__cvta_generic_to_shared(sdst);
    asm volatile("cp.async.cg.shared.global [%0], [%1], 16;" :: "r"(s), "l"(gsrc) : "memory");
}
__device__ __forceinline__ void cp_commit() {
    asm volatile("cp.async.commit_group;" ::: "memory");
}
template<int N>
__device__ __forceinline__ void cp_wait() {
    asm volatile("cp.async.wait_group %0;" :: "n"(N) : "memory");
}

// ---------------- device scratch (no allocation allowed) ----------------
__device__ __align__(16) u32   g_hb [MAXN * (size_t)(HID / 2)]; // bf16x2 GEMM output
__device__ __align__(16) float g_acc[MAXN * (size_t)HID];       // relu'd layer-1 output (f32)
__device__ __align__(16) float2 g_edge[MAXE];                   // {row bits, dis[row]*ew}
__device__ u64   g_degcnt[MAXN];         // (cnt << 44) | (weight sum in 2^-32 units)
__device__ float g_dis [MAXN];
__device__ int   g_off [MAXN + 1];
__device__ int   g_cur [MAXN];
__device__ int   g_bsum[(MAXN + SCAN_B - 1) / SCAN_B];
__device__ int   g_boff[(MAXN + SCAN_B - 1) / SCAN_B];
__device__ int   g_gs  [G_NUM + 1];
__device__ int   g_scan_done;
__device__ __align__(16) float g_sums[G_NUM * HID];

// ================= GEMM body (device function; callable from fused kernels) ==
// g_hb[row0..row0+128][HID] = bf16( X[.][K] @ W[K][HID] )
// 3-stage cp.async pipeline, KCH=16, one __syncthreads per chunk.
template<int K, bool SRC_ACC>
__device__ __forceinline__ void gemm_body(const float* __restrict__ X,
                                          const float* __restrict__ W,
                                          int n, int bid) {
    constexpr int KCH = 16;
    constexpr int SXS = KCH + 4;                 // 20-float padded x row stride
    constexpr int SWS = HID + 4;                 // 68-float w row stride
    constexpr int NCH = K / KCH;
    __shared__ float sx[3][128 * SXS];
    __shared__ float sw[3][KCH * SWS];
    const int t = threadIdx.x;
    const int row0 = bid * 128;
    const int hq  = (t & 7) * 8;                 // col start (floats)
    const int hqs = hq + ((t & 7) >> 2) * 4;     // bank-shifted smem col
    const int rg  = t >> 3;                      // 0..31
    const float* xbase = SRC_ACC ? g_acc : X;

    auto stage = [&](int ch, int buf) {
        #pragma unroll
        for (int i = t; i < 128 * (KCH / 4); i += 256) {
            const int r = i >> 2, c = i & 3;
            const int gr = min(row0 + r, n - 1);
            cp16(&sx[buf][r * SXS + c * 4],
                 xbase + (size_t)gr * K + ch * KCH + c * 4);
        }
        {   // 256 float4 of W per chunk: one per thread
            const int k = t >> 4, c4 = t & 15;
            cp16(&sw[buf][k * SWS + c4 * 4 + (c4 >= 8 ? 4 : 0)],
                 W + (size_t)(ch * KCH + k) * HID + c4 * 4);
        }
        cp_commit();
    };

    u64 acc[4][4];
    #pragma unroll
    for (int i = 0; i < 4; i++)
        #pragma unroll
        for (int j = 0; j < 4; j++) acc[i][j] = 0;

    stage(0, 0);
    stage(1, 1);
    #pragma unroll
    for (int ch = 0; ch < NCH; ch++) {
        const int buf = ch % 3;
        if (ch + 1 < NCH) cp_wait<1>(); else cp_wait<0>();
        __syncthreads();
        if (ch + 2 < NCH) stage(ch + 2, (ch + 2) % 3);

        #pragma unroll
        for (int qd = 0; qd < KCH / 4; qd++) {
            float4 xr[4];
            #pragma unroll
            for (int i = 0; i < 4; i++)
                xr[i] = *(const float4*)(&sx[buf][(rg + 32 * i) * SXS + qd * 4]);
            #pragma unroll
            for (int kk = 0; kk < 4; kk++) {
                const float* wrow = &sw[buf][(qd * 4 + kk) * SWS];
                const float4 w0 = *(const float4*)(wrow + hqs);
                const float4 w1 = *(const float4*)(wrow + hqs + 4);
                const u64 wp0 = pack2(w0.x, w0.y);
                const u64 wp1 = pack2(w0.z, w0.w);
                const u64 wp2 = pack2(w1.x, w1.y);
                const u64 wp3 = pack2(w1.z, w1.w);
                #pragma unroll
                for (int i = 0; i < 4; i++) {
                    const float xv = ((const float*)&xr[i])[kk];
                    const u64 xp = pack2(xv, xv);
                    acc[i][0] = ffma2(xp, wp0, acc[i][0]);
                    acc[i][1] = ffma2(xp, wp1, acc[i][1]);
                    acc[i][2] = ffma2(xp, wp2, acc[i][2]);
                    acc[i][3] = ffma2(xp, wp3, acc[i][3]);
                }
            }
        }
    }

    #pragma unroll
    for (int i = 0; i < 4; i++) {
        const int gr = row0 + rg + 32 * i;
        if (gr < n) {
            uint4 o;
            float2 f0 = unpack2(acc[i][0]); o.x = cvt_bf16x2(f0.x, f0.y);
            float2 f1 = unpack2(acc[i][1]); o.y = cvt_bf16x2(f1.x, f1.y);
            float2 f2 = unpack2(acc[i][2]); o.z = cvt_bf16x2(f2.x, f2.y);
            float2 f3 = unpack2(acc[i][3]); o.w = cvt_bf16x2(f3.x, f3.y);
            *(uint4*)(g_hb + (size_t)gr * (HID / 2) + (t & 7) * 4) = o;
        }
    }
}

// ============== gather body: out[8] = relu(layer(node)) for lane q ==========
__device__ __forceinline__ void gather_node(int node, int q,
                                            const float* __restrict__ b,
                                            float* out) {
    int e = g_off[node];
    const int e_end = g_off[node + 1];

    u64 a0 = 0, a1 = 0, a2 = 0, a3 = 0;

    for (; e + 3 < e_end; e += 4) {
        float2 rA = g_edge[e];
        float2 rB = g_edge[e + 1];
        float2 rC = g_edge[e + 2];
        float2 rD = g_edge[e + 3];
        uint4 hA = *(const uint4*)(g_hb + (size_t)__float_as_int(rA.x) * (HID / 2) + q * 4);
        uint4 hB = *(const uint4*)(g_hb + (size_t)__float_as_int(rB.x) * (HID / 2) + q * 4);
        uint4 hC = *(const uint4*)(g_hb + (size_t)__float_as_int(rC.x) * (HID / 2) + q * 4);
        uint4 hD = *(const uint4*)(g_hb + (size_t)__float_as_int(rD.x) * (HID / 2) + q * 4);
        const u64 nA = pack2(rA.y, rA.y), nB = pack2(rB.y, rB.y);
        const u64 nC = pack2(rC.y, rC.y), nD = pack2(rD.y, rD.y);
        a0 = ffma2(nA, bf2f2(hA.x), a0); a1 = ffma2(nA, bf2f2(hA.y), a1);
        a2 = ffma2(nA, bf2f2(hA.z), a2); a3 = ffma2(nA, bf2f2(hA.w), a3);
        a0 = ffma2(nB, bf2f2(hB.x), a0); a1 = ffma2(nB, bf2f2(hB.y), a1);
        a2 = ffma2(nB, bf2f2(hB.z), a2); a3 = ffma2(nB, bf2f2(hB.w), a3);
        a0 = ffma2(nC, bf2f2(hC.x), a0); a1 = ffma2(nC, bf2f2(hC.y), a1);
        a2 = ffma2(nC, bf2f2(hC.z), a2); a3 = ffma2(nC, bf2f2(hC.w), a3);
        a0 = ffma2(nD, bf2f2(hD.x), a0); a1 = ffma2(nD, bf2f2(hD.y), a1);
        a2 = ffma2(nD, bf2f2(hD.z), a2); a3 = ffma2(nD, bf2f2(hD.w), a3);
    }
    for (; e < e_end; e++) {
        float2 r0 = g_edge[e];
        uint4 h0 = *(const uint4*)(g_hb + (size_t)__float_as_int(r0.x) * (HID / 2) + q * 4);
        const u64 n0 = pack2(r0.y, r0.y);
        a0 = ffma2(n0, bf2f2(h0.x), a0); a1 = ffma2(n0, bf2f2(h0.y), a1);
        a2 = ffma2(n0, bf2f2(h0.z), a2); a3 = ffma2(n0, bf2f2(h0.w), a3);
    }

    const float d  = g_dis[node];
    const float dd = d * d;
    const uint4 hs = *(const uint4*)(g_hb + (size_t)node * (HID / 2) + q * 4);
    const float* bb = b + q * 8;
    u64 aa[4] = {a0, a1, a2, a3};
    u32 hh[4] = {hs.x, hs.y, hs.z, hs.w};
    #pragma unroll
    for (int j = 0; j < 4; j++) {
        float2 s = unpack2(bf2f2(hh[j]));
        float2 ev = unpack2(aa[j]);
        out[2*j]   = fmaxf(bb[2*j]   + dd * s.x + d * ev.x, 0.0f);
        out[2*j+1] = fmaxf(bb[2*j+1] + dd * s.y + d * ev.y, 0.0f);
    }
}

// ---------------- prolog / fused kernels ----------------

__global__ void k_reset(int n) {
    int i = blockIdx.x * blockDim.x + threadIdx.x;
    if (i < n)           g_degcnt[i] = 0;
    if (i < G_NUM * HID) g_sums[i] = 0.0f;
    if (i == 0)          g_scan_done = 0;
}

// fused: blocks [0,gB) run GEMM1 rows [0, gB*128); the rest run the degree histogram
__global__ void __launch_bounds__(256) k_deg_gemm1(
    const int* __restrict__ col, const float* __restrict__ ew, int E,
    const float* __restrict__ x, const float* __restrict__ W1, int n, int gB) {
    if ((int)blockIdx.x < gB) {
        gemm_body<IN_DIM, false>(x, W1, n, blockIdx.x);
        return;
    }
    int e = ((int)blockIdx.x - gB) * 256 + threadIdx.x;
    if (e < E) {
        int c = col[e];
        u64 v = (1ull << 44) | (u64)(ew[e] * 4294967296.0f);
        atomicAdd(&g_degcnt[c], v);   // one integer RMW: count + weight sum
    }
}

// block-local exclusive scan over counts (+ dis = rsqrt(deg));
// last-arriving block also scans the block sums (replaces k_scan2)
__global__ void k_scan1(int n) {
    __shared__ int s[2][SCAN_B];
    __shared__ int lastflag;
    const int t = threadIdx.x;
    const int i = blockIdx.x * SCAN_B + t;
    int v = 0;
    if (i < n) {
        u64 dc = g_degcnt[i];
        v = (int)(dc >> 44);
        g_dis[i] = rsqrtf(1.0f + (float)(dc & 0xFFFFFFFFFFFull) * 2.3283064365386963e-10f);
    }
    s[0][t] = v;
    __syncthreads();
    int src = 0;
    #pragma unroll
    for (int d = 1; d < SCAN_B; d <<= 1) {
        int x = s[src][t];
        if (t >= d) x += s[src][t - d];
        s[1 - src][t] = x;
        src = 1 - src;
        __syncthreads();
    }
    int incl = s[src][t];
    if (i < n) g_off[i] = incl - v;
    if (t == SCAN_B - 1) g_bsum[blockIdx.x] = incl;

    // single-pass: last block scans the (<=128) block sums into g_boff
    __threadfence();
    if (t == 0) lastflag = (atomicAdd(&g_scan_done, 1) == (int)gridDim.x - 1);
    __syncthreads();
    if (!lastflag) return;
    const int nb = gridDim.x;
    int bv = 0;
    if (t < 128) {
        bv = (t < nb) ? *(volatile int*)&g_bsum[t] : 0;
        s[0][t] = bv;
    }
    __syncthreads();
    #pragma unroll
    for (int d = 1; d < 128; d <<= 1) {
        int x = 0;
        if (t < 128) { x = s[0][t]; if (t >= d) x += s[0][t - d]; }
        __syncthreads();
        if (t < 128) s[0][t] = x;
        __syncthreads();
    }
    if (t < nb) g_boff[t] = s[0][t] - bv;
}

__global__ void k_scan3(const int* __restrict__ batch, int n, int E) {
    int i = blockIdx.x * blockDim.x + threadIdx.x;
    if (i >= n) return;
    int o = g_off[i] + g_boff[i >> 10];
    g_off[i] = o;
    g_cur[i] = o;
    if (i == 0) g_off[n] = E;
    int b = batch[i];
    int p = (i == 0) ? -1 : batch[i - 1];
    for (int g = p + 1; g <= b; ++g) g_gs[g] = i;
    if (i == n - 1)
        for (int g = b + 1; g <= G_NUM; ++g) g_gs[g] = n;
}

// fused: blocks [0,gB) run GEMM1 rows [rowBase*128, ...); the rest place edges
__global__ void __launch_bounds__(256) k_place_gemm1(
    const int* __restrict__ row, const int* __restrict__ col,
    const float* __restrict__ ew, int E,
    const float* __restrict__ x, const float* __restrict__ W1, int n,
    int gB, int rowBase) {
    if ((int)blockIdx.x < gB) {
        gemm_body<IN_DIM, false>(x, W1, n, rowBase + blockIdx.x);
        return;
    }
    int e = ((int)blockIdx.x - gB) * 256 + threadIdx.x;
    if (e >= E) return;
    int r = row[e];
    int c = col[e];
    float nm = g_dis[r] * ew[e];
    int pos = atomicAdd(&g_cur[c], 1);
    g_edge[pos] = make_float2(__int_as_float(r), nm);
}

// standalone GEMM2
__global__ void __launch_bounds__(256) k_gemm2(const float* __restrict__ W, int n) {
    gemm_body<HID, true>(nullptr, W, n, blockIdx.x);
}

// layer-1 gather: one node per 8-lane group, writes g_acc (gemm2 input)
__global__ void k_gather(const float* __restrict__ b, int n) {
    int tid = blockIdx.x * blockDim.x + threadIdx.x;
    int node = tid >> 3;
    if (node >= n) return;
    const int q = tid & 7;
    float out[8];
    gather_node(node, q, b, out);
    float* dst = g_acc + (size_t)node * HID + q * 8;
    *(float4*)(dst)     = make_float4(out[0], out[1], out[2], out[3]);
    *(float4*)(dst + 4) = make_float4(out[4], out[5], out[6], out[7]);
}

// layer-2 gather fused with mean-pool accumulation: each 8-lane group owns
// NPG contiguous nodes; relu'd results accumulate in registers, flushed to
// g_sums via red.add on graph change / end.
__global__ void k_gather_pool(const float* __restrict__ b,
                              const int* __restrict__ batch, int n) {
    const int t = threadIdx.x;
    const int q = t & 7;
    const int grp = blockIdx.x * 32 + (t >> 3);
    int node = grp * NPG;
    if (node >= n) return;
    const int node_end = min(node + NPG, n);

    float pacc[8] = {0, 0, 0, 0, 0, 0, 0, 0};
    int cur_g = batch[node];

    for (; node < node_end; node++) {
        float out[8];
        gather_node(node, q, b, out);
        int bg = batch[node];
        if (bg != cur_g) {
            float* dst = g_sums + cur_g * HID + q * 8;
            #pragma unroll
            for (int j = 0; j < 8; j++) atomicAdd(dst + j, pacc[j]);
            #pragma unroll
            for (int j = 0; j < 8; j++) pacc[j] = 0.0f;
            cur_g = bg;
        }
        #pragma unroll
        for (int j = 0; j < 8; j++) pacc[j] += out[j];
    }
    float* dst = g_sums + cur_g * HID + q * 8;
    #pragma unroll
    for (int j = 0; j < 8; j++) atomicAdd(dst + j, pacc[j]);
}

__global__ void k_final(const float* __restrict__ Wc,
                        const float* __restrict__ bc,
                        float* __restrict__ out) {
    int g = blockIdx.x * blockDim.x + threadIdx.x;
    if (g >= G_NUM) return;
    const float c = fmaxf((float)(g_gs[g + 1] - g_gs[g]), 1.0f);
    float acc = 0.0f;
    #pragma unroll
    for (int h = 0; h < HID; h++)
        acc += g_sums[g * HID + h] * Wc[h];
    out[g] = acc / c + bc[0];
}

// ---------------- launcher ----------------
extern "C" void kernel_launch(void* const* d_in, const int* in_sizes, int n_in,
                              void* d_out, int out_size) {
    const float* x     = (const float*)d_in[0];
    const int*   ei    = (const int*)  d_in[1];   // int32 (JAX x64 disabled)
    const float* ew    = (const float*)d_in[2];
    const int*   batch = (const int*)  d_in[3];
    const float* W1    = (const float*)d_in[4];
    const float* b1    = (const float*)d_in[5];
    const float* W2    = (const float*)d_in[6];
    const float* b2    = (const float*)d_in[7];
    const float* Wc    = (const float*)d_in[8];
    const float* bc    = (const float*)d_in[9];
    float* out = (float*)d_out;

    const int n = in_sizes[0] / IN_DIM;   // 100000
    const int E = in_sizes[2];            // 3200000
    const int* row = ei;
    const int* col = ei + E;
    const int T = 256;
    const int nb = (n + SCAN_B - 1) / SCAN_B;
    const int nblk  = (n + 127) / 128;    // 782 GEMM row-blocks
    const int half1 = (nblk + 1) / 2;     // 391
    const int half2 = nblk - half1;       // 391
    const int eblk  = (E + T - 1) / T;    // 12500 edge blocks

    k_reset<<<(n + T - 1) / T, T>>>(n);
    // GEMM1 (first half) overlapped with packed degree histogram
    k_deg_gemm1<<<half1 + eblk, T>>>(col, ew, E, x, W1, n, half1);
    k_scan1<<<nb, SCAN_B>>>(n);           // includes block-sum scan (was scan2)
    k_scan3<<<(n + T - 1) / T, T>>>(batch, n, E);
    // GEMM1 (second half) overlapped with edge placement
    k_place_gemm1<<<half2 + eblk, T>>>(row, col, ew, E, x, W1, n, half2, half1);

    k_gather<<<(n * 8 + T - 1) / T, T>>>(b1, n);              // layer 1 -> g_acc

    k_gemm2<<<nblk, T>>>(W2, n);                              // layer 2 GEMM
    k_gather_pool<<<(n + 32 * NPG - 1) / (32 * NPG), T>>>(b2, batch, n); // layer 2 + pool

    k_final<<<1, T>>>(Wc, bc, out);
}

// round 14
// speedup vs baseline: 1.0729x; 1.0729x over previous
#include <cuda_runtime.h>

#define MAXN   100000
#define MAXE   3200000
#define IN_DIM 128
#define HID    64
#define G_NUM  256
#define SCAN_B 1024

typedef unsigned long long u64;
typedef unsigned int u32;

// ---- packed fp32x2 helpers (sm_100+) ----
__device__ __forceinline__ u64 pack2(float lo, float hi) {
    u64 r; asm("mov.b64 %0, {%1, %2};" : "=l"(r) : "f"(lo), "f"(hi)); return r;
}
__device__ __forceinline__ u64 ffma2(u64 a, u64 b, u64 c) {
    u64 d; asm("fma.rn.f32x2 %0, %1, %2, %3;" : "=l"(d) : "l"(a), "l"(b), "l"(c)); return d;
}
__device__ __forceinline__ float2 unpack2(u64 v) {
    float2 f; asm("mov.b64 {%0, %1}, %2;" : "=f"(f.x), "=f"(f.y) : "l"(v)); return f;
}
__device__ __forceinline__ u32 cvt_bf16x2(float lo, float hi) {
    u32 r; asm("cvt.rn.bf16x2.f32 %0, %1, %2;" : "=r"(r) : "f"(hi), "f"(lo)); return r;
}
__device__ __forceinline__ u64 bf2f2(u32 u) {
    u32 lo = u << 16;
    u32 hi = u & 0xFFFF0000u;
    u64 r; asm("mov.b64 %0, {%1, %2};" : "=l"(r) : "r"(lo), "r"(hi)); return r;
}
// ---- cp.async helpers ----
__device__ __forceinline__ void cp16(void* sdst, const void* gsrc) {
    u32 s = (u32)__cvta_generic_to_shared(sdst);
    asm volatile("cp.async.cg.shared.global [%0], [%1], 16;" :: "r"(s), "l"(gsrc) : "memory");
}
__device__ __forceinline__ void cp_commit() {
    asm volatile("cp.async.commit_group;" ::: "memory");
}
template<int N>
__device__ __forceinline__ void cp_wait() {
    asm volatile("cp.async.wait_group %0;" :: "n"(N) : "memory");
}

// ---------------- device scratch (no allocation allowed) ----------------
__device__ __align__(16) u32   g_hb [MAXN * (size_t)(HID / 2)]; // bf16x2 GEMM output
__device__ __align__(16) float g_acc[MAXN * (size_t)HID];       // relu'd layer output (f32)
__device__ __align__(16) float2 g_edge[MAXE];                   // {row bits, dis[row]*ew}
__device__ u64   g_degcnt[MAXN];         // (cnt << 44) | (weight sum in 2^-32 units)
__device__ float g_dis [MAXN];
__device__ int   g_off [MAXN + 1];
__device__ int   g_cur [MAXN];
__device__ int   g_bsum[(MAXN + SCAN_B - 1) / SCAN_B];
__device__ int   g_boff[(MAXN + SCAN_B - 1) / SCAN_B];
__device__ int   g_gs  [G_NUM + 1];
__device__ int   g_scan_done;
__device__ __align__(16) float g_sums[G_NUM * HID];

// ================= GEMM body =================================================
// g_hb[row0..row0+128][HID] = bf16( X[.][K] @ W[K][HID] )
// 3-stage cp.async pipeline, KCH=16, one __syncthreads per chunk.
template<int K, bool SRC_ACC>
__device__ __forceinline__ void gemm_body(const float* __restrict__ X,
                                          const float* __restrict__ W,
                                          int n, int bid) {
    constexpr int KCH = 16;
    constexpr int SXS = KCH + 4;
    constexpr int SWS = HID + 4;
    constexpr int NCH = K / KCH;
    __shared__ float sx[3][128 * SXS];
    __shared__ float sw[3][KCH * SWS];
    const int t = threadIdx.x;
    const int row0 = bid * 128;
    const int hq  = (t & 7) * 8;
    const int hqs = hq + ((t & 7) >> 2) * 4;
    const int rg  = t >> 3;
    const float* xbase = SRC_ACC ? g_acc : X;

    auto stage = [&](int ch, int buf) {
        #pragma unroll
        for (int i = t; i < 128 * (KCH / 4); i += 256) {
            const int r = i >> 2, c = i & 3;
            const int gr = min(row0 + r, n - 1);
            cp16(&sx[buf][r * SXS + c * 4],
                 xbase + (size_t)gr * K + ch * KCH + c * 4);
        }
        {
            const int k = t >> 4, c4 = t & 15;
            cp16(&sw[buf][k * SWS + c4 * 4 + (c4 >= 8 ? 4 : 0)],
                 W + (size_t)(ch * KCH + k) * HID + c4 * 4);
        }
        cp_commit();
    };

    u64 acc[4][4];
    #pragma unroll
    for (int i = 0; i < 4; i++)
        #pragma unroll
        for (int j = 0; j < 4; j++) acc[i][j] = 0;

    stage(0, 0);
    stage(1, 1);
    #pragma unroll
    for (int ch = 0; ch < NCH; ch++) {
        const int buf = ch % 3;
        if (ch + 1 < NCH) cp_wait<1>(); else cp_wait<0>();
        __syncthreads();
        if (ch + 2 < NCH) stage(ch + 2, (ch + 2) % 3);

        #pragma unroll
        for (int qd = 0; qd < KCH / 4; qd++) {
            float4 xr[4];
            #pragma unroll
            for (int i = 0; i < 4; i++)
                xr[i] = *(const float4*)(&sx[buf][(rg + 32 * i) * SXS + qd * 4]);
            #pragma unroll
            for (int kk = 0; kk < 4; kk++) {
                const float* wrow = &sw[buf][(qd * 4 + kk) * SWS];
                const float4 w0 = *(const float4*)(wrow + hqs);
                const float4 w1 = *(const float4*)(wrow + hqs + 4);
                const u64 wp0 = pack2(w0.x, w0.y);
                const u64 wp1 = pack2(w0.z, w0.w);
                const u64 wp2 = pack2(w1.x, w1.y);
                const u64 wp3 = pack2(w1.z, w1.w);
                #pragma unroll
                for (int i = 0; i < 4; i++) {
                    const float xv = ((const float*)&xr[i])[kk];
                    const u64 xp = pack2(xv, xv);
                    acc[i][0] = ffma2(xp, wp0, acc[i][0]);
                    acc[i][1] = ffma2(xp, wp1, acc[i][1]);
                    acc[i][2] = ffma2(xp, wp2, acc[i][2]);
                    acc[i][3] = ffma2(xp, wp3, acc[i][3]);
                }
            }
        }
    }

    #pragma unroll
    for (int i = 0; i < 4; i++) {
        const int gr = row0 + rg + 32 * i;
        if (gr < n) {
            uint4 o;
            float2 f0 = unpack2(acc[i][0]); o.x = cvt_bf16x2(f0.x, f0.y);
            float2 f1 = unpack2(acc[i][1]); o.y = cvt_bf16x2(f1.x, f1.y);
            float2 f2 = unpack2(acc[i][2]); o.z = cvt_bf16x2(f2.x, f2.y);
            float2 f3 = unpack2(acc[i][3]); o.w = cvt_bf16x2(f3.x, f3.y);
            *(uint4*)(g_hb + (size_t)gr * (HID / 2) + (t & 7) * 4) = o;
        }
    }
}

// ---------------- prolog / fused kernels ----------------

__global__ void k_reset(int n) {
    int i = blockIdx.x * blockDim.x + threadIdx.x;
    if (i < n)  g_degcnt[i] = 0;
    if (i == 0) g_scan_done = 0;
}

// fused: blocks [0,gB) run GEMM1 rows [0, gB*128); the rest run the degree histogram
__global__ void __launch_bounds__(256) k_deg_gemm1(
    const int* __restrict__ col, const float* __restrict__ ew, int E,
    const float* __restrict__ x, const float* __restrict__ W1, int n, int gB) {
    if ((int)blockIdx.x < gB) {
        gemm_body<IN_DIM, false>(x, W1, n, blockIdx.x);
        return;
    }
    int e = ((int)blockIdx.x - gB) * 256 + threadIdx.x;
    if (e < E) {
        int c = col[e];
        u64 v = (1ull << 44) | (u64)(ew[e] * 4294967296.0f);
        atomicAdd(&g_degcnt[c], v);   // one integer RMW: count + weight sum
    }
}

// block-local exclusive scan over counts (+ dis = rsqrt(deg));
// last-arriving block also scans the block sums (single-pass scan)
__global__ void k_scan1(int n) {
    __shared__ int s[2][SCAN_B];
    __shared__ int lastflag;
    const int t = threadIdx.x;
    const int i = blockIdx.x * SCAN_B + t;
    int v = 0;
    if (i < n) {
        u64 dc = g_degcnt[i];
        v = (int)(dc >> 44);
        g_dis[i] = rsqrtf(1.0f + (float)(dc & 0xFFFFFFFFFFFull) * 2.3283064365386963e-10f);
    }
    s[0][t] = v;
    __syncthreads();
    int src = 0;
    #pragma unroll
    for (int d = 1; d < SCAN_B; d <<= 1) {
        int x = s[src][t];
        if (t >= d) x += s[src][t - d];
        s[1 - src][t] = x;
        src = 1 - src;
        __syncthreads();
    }
    int incl = s[src][t];
    if (i < n) g_off[i] = incl - v;
    if (t == SCAN_B - 1) g_bsum[blockIdx.x] = incl;

    __threadfence();
    if (t == 0) lastflag = (atomicAdd(&g_scan_done, 1) == (int)gridDim.x - 1);
    __syncthreads();
    if (!lastflag) return;
    const int nb = gridDim.x;
    int bv = 0;
    if (t < 128) {
        bv = (t < nb) ? *(volatile int*)&g_bsum[t] : 0;
        s[0][t] = bv;
    }
    __syncthreads();
    #pragma unroll
    for (int d = 1; d < 128; d <<= 1) {
        int x = 0;
        if (t < 128) { x = s[0][t]; if (t >= d) x += s[0][t - d]; }
        __syncthreads();
        if (t < 128) s[0][t] = x;
        __syncthreads();
    }
    if (t < nb) g_boff[t] = s[0][t] - bv;
}

__global__ void k_scan3(const int* __restrict__ batch, int n, int E) {
    int i = blockIdx.x * blockDim.x + threadIdx.x;
    if (i >= n) return;
    int o = g_off[i] + g_boff[i >> 10];
    g_off[i] = o;
    g_cur[i] = o;
    if (i == 0) g_off[n] = E;
    int b = batch[i];
    int p = (i == 0) ? -1 : batch[i - 1];
    for (int g = p + 1; g <= b; ++g) g_gs[g] = i;
    if (i == n - 1)
        for (int g = b + 1; g <= G_NUM; ++g) g_gs[g] = n;
}

// fused: blocks [0,gB) run GEMM1 rows [rowBase*128, ...); the rest place edges
__global__ void __launch_bounds__(256) k_place_gemm1(
    const int* __restrict__ row, const int* __restrict__ col,
    const float* __restrict__ ew, int E,
    const float* __restrict__ x, const float* __restrict__ W1, int n,
    int gB, int rowBase) {
    if ((int)blockIdx.x < gB) {
        gemm_body<IN_DIM, false>(x, W1, n, rowBase + blockIdx.x);
        return;
    }
    int e = ((int)blockIdx.x - gB) * 256 + threadIdx.x;
    if (e >= E) return;
    int r = row[e];
    int c = col[e];
    float nm = g_dis[r] * ew[e];
    int pos = atomicAdd(&g_cur[c], 1);
    g_edge[pos] = make_float2(__int_as_float(r), nm);
}

// standalone GEMM2
__global__ void __launch_bounds__(256) k_gemm2(const float* __restrict__ W, int n) {
    gemm_body<HID, true>(nullptr, W, n, blockIdx.x);
}

// ---------------- per-node CSR gather (bf16 h), relu applied at store --------
// 8 lanes/node, lane owns 8 cols (one uint4 of bf16x2 per edge = 16B).
__global__ void k_gather(const float* __restrict__ b, int n) {
    int tid = blockIdx.x * blockDim.x + threadIdx.x;
    int node = tid >> 3;
    if (node >= n) return;
    const int q = tid & 7;

    int e = g_off[node];
    const int e_end = g_off[node + 1];

    u64 a0 = 0, a1 = 0, a2 = 0, a3 = 0;

    for (; e + 3 < e_end; e += 4) {
        float2 rA = g_edge[e];
        float2 rB = g_edge[e + 1];
        float2 rC = g_edge[e + 2];
        float2 rD = g_edge[e + 3];
        uint4 hA = *(const uint4*)(g_hb + (size_t)__float_as_int(rA.x) * (HID / 2) + q * 4);
        uint4 hB = *(const uint4*)(g_hb + (size_t)__float_as_int(rB.x) * (HID / 2) + q * 4);
        uint4 hC = *(const uint4*)(g_hb + (size_t)__float_as_int(rC.x) * (HID / 2) + q * 4);
        uint4 hD = *(const uint4*)(g_hb + (size_t)__float_as_int(rD.x) * (HID / 2) + q * 4);
        const u64 nA = pack2(rA.y, rA.y), nB = pack2(rB.y, rB.y);
        const u64 nC = pack2(rC.y, rC.y), nD = pack2(rD.y, rD.y);
        a0 = ffma2(nA, bf2f2(hA.x), a0); a1 = ffma2(nA, bf2f2(hA.y), a1);
        a2 = ffma2(nA, bf2f2(hA.z), a2); a3 = ffma2(nA, bf2f2(hA.w), a3);
        a0 = ffma2(nB, bf2f2(hB.x), a0); a1 = ffma2(nB, bf2f2(hB.y), a1);
        a2 = ffma2(nB, bf2f2(hB.z), a2); a3 = ffma2(nB, bf2f2(hB.w), a3);
        a0 = ffma2(nC, bf2f2(hC.x), a0); a1 = ffma2(nC, bf2f2(hC.y), a1);
        a2 = ffma2(nC, bf2f2(hC.z), a2); a3 = ffma2(nC, bf2f2(hC.w), a3);
        a0 = ffma2(nD, bf2f2(hD.x), a0); a1 = ffma2(nD, bf2f2(hD.y), a1);
        a2 = ffma2(nD, bf2f2(hD.z), a2); a3 = ffma2(nD, bf2f2(hD.w), a3);
    }
    for (; e < e_end; e++) {
        float2 r0 = g_edge[e];
        uint4 h0 = *(const uint4*)(g_hb + (size_t)__float_as_int(r0.x) * (HID / 2) + q * 4);
        const u64 n0 = pack2(r0.y, r0.y);
        a0 = ffma2(n0, bf2f2(h0.x), a0); a1 = ffma2(n0, bf2f2(h0.y), a1);
        a2 = ffma2(n0, bf2f2(h0.z), a2); a3 = ffma2(n0, bf2f2(h0.w), a3);
    }

    const float d  = g_dis[node];
    const float dd = d * d;
    const uint4 hs = *(const uint4*)(g_hb + (size_t)node * (HID / 2) + q * 4);
    const float* bb = b + q * 8;
    float out[8];
    u64 aa[4] = {a0, a1, a2, a3};
    u32 hh[4] = {hs.x, hs.y, hs.z, hs.w};
    #pragma unroll
    for (int j = 0; j < 4; j++) {
        float2 s = unpack2(bf2f2(hh[j]));
        float2 ev = unpack2(aa[j]);
        out[2*j]   = fmaxf(bb[2*j]   + dd * s.x + d * ev.x, 0.0f);
        out[2*j+1] = fmaxf(bb[2*j+1] + dd * s.y + d * ev.y, 0.0f);
    }
    float* dst = g_acc + (size_t)node * HID + q * 8;
    *(float4*)(dst)     = make_float4(out[0], out[1], out[2], out[3]);
    *(float4*)(dst + 4) = make_float4(out[4], out[5], out[6], out[7]);
}

// ---------------- pool + head (g_acc already relu'd) ----------------
__global__ void k_pool(int n) {
    const int g = blockIdx.x;
    const int t = threadIdx.x;
    const int q = t & 15;
    const int sub = t >> 4;
    const int s = g_gs[g], e = g_gs[g + 1];

    float4 acc = make_float4(0.f, 0.f, 0.f, 0.f);
    for (int i = s + sub; i < e; i += 16) {
        float4 v = ((const float4*)(g_acc + (size_t)i * HID))[q];
        acc.x += v.x; acc.y += v.y; acc.z += v.z; acc.w += v.w;
    }
    __shared__ float4 sm[256];
    sm[t] = acc;
    __syncthreads();
    if (sub == 0) {
        float4 a = acc;
        #pragma unroll
        for (int k = 1; k < 16; k++) {
            float4 bb = sm[k * 16 + q];
            a.x += bb.x; a.y += bb.y; a.z += bb.z; a.w += bb.w;
        }
        ((float4*)(g_sums + g * HID))[q] = a;
    }
}

__global__ void k_final(const float* __restrict__ Wc,
                        const float* __restrict__ bc,
                        float* __restrict__ out) {
    int g = blockIdx.x * blockDim.x + threadIdx.x;
    if (g >= G_NUM) return;
    const float c = fmaxf((float)(g_gs[g + 1] - g_gs[g]), 1.0f);
    float acc = 0.0f;
    #pragma unroll
    for (int h = 0; h < HID; h++)
        acc += g_sums[g * HID + h] * Wc[h];
    out[g] = acc / c + bc[0];
}

// ---------------- launcher ----------------
extern "C" void kernel_launch(void* const* d_in, const int* in_sizes, int n_in,
                              void* d_out, int out_size) {
    const float* x     = (const float*)d_in[0];
    const int*   ei    = (const int*)  d_in[1];   // int32 (JAX x64 disabled)
    const float* ew    = (const float*)d_in[2];
    const int*   batch = (const int*)  d_in[3];
    const float* W1    = (const float*)d_in[4];
    const float* b1    = (const float*)d_in[5];
    const float* W2    = (const float*)d_in[6];
    const float* b2    = (const float*)d_in[7];
    const float* Wc    = (const float*)d_in[8];
    const float* bc    = (const float*)d_in[9];
    float* out = (float*)d_out;

    const int n = in_sizes[0] / IN_DIM;   // 100000
    const int E = in_sizes[2];            // 3200000
    const int* row = ei;
    const int* col = ei + E;
    const int T = 256;
    const int nb = (n + SCAN_B - 1) / SCAN_B;
    const int nblk  = (n + 127) / 128;    // 782 GEMM row-blocks
    const int half1 = (nblk + 1) / 2;
    const int half2 = nblk - half1;
    const int eblk  = (E + T - 1) / T;

    k_reset<<<(n + T - 1) / T, T>>>(n);
    // GEMM1 (first half) overlapped with packed degree histogram
    k_deg_gemm1<<<half1 + eblk, T>>>(col, ew, E, x, W1, n, half1);
    k_scan1<<<nb, SCAN_B>>>(n);           // includes block-sum scan
    k_scan3<<<(n + T - 1) / T, T>>>(batch, n, E);
    // GEMM1 (second half) overlapped with edge placement
    k_place_gemm1<<<half2 + eblk, T>>>(row, col, ew, E, x, W1, n, half2, half1);

    k_gather<<<(n * 8 + T - 1) / T, T>>>(b1, n);              // layer 1 -> g_acc

    k_gemm2<<<nblk, T>>>(W2, n);                              // layer 2 GEMM
    k_gather<<<(n * 8 + T - 1) / T, T>>>(b2, n);              // layer 2 -> g_acc

    k_pool <<<G_NUM, 256>>>(n);
    k_final<<<1, T>>>(Wc, bc, out);
}

// round 15
// speedup vs baseline: 1.0940x; 1.0196x over previous
#include <cuda_runtime.h>

#define MAXN   100000
#define MAXE   3200000
#define IN_DIM 128
#define HID    64
#define G_NUM  256
#define SCAN_B 1024
#define NBMAX  ((MAXN + SCAN_B - 1) / SCAN_B)

typedef unsigned long long u64;
typedef unsigned int u32;

// ---- packed fp32x2 helpers (sm_100+) ----
__device__ __forceinline__ u64 pack2(float lo, float hi) {
    u64 r; asm("mov.b64 %0, {%1, %2};" : "=l"(r) : "f"(lo), "f"(hi)); return r;
}
__device__ __forceinline__ u64 ffma2(u64 a, u64 b, u64 c) {
    u64 d; asm("fma.rn.f32x2 %0, %1, %2, %3;" : "=l"(d) : "l"(a), "l"(b), "l"(c)); return d;
}
__device__ __forceinline__ float2 unpack2(u64 v) {
    float2 f; asm("mov.b64 {%0, %1}, %2;" : "=f"(f.x), "=f"(f.y) : "l"(v)); return f;
}
__device__ __forceinline__ u32 cvt_bf16x2(float lo, float hi) {
    u32 r; asm("cvt.rn.bf16x2.f32 %0, %1, %2;" : "=r"(r) : "f"(hi), "f"(lo)); return r;
}
__device__ __forceinline__ u64 bf2f2(u32 u) {
    u32 lo = u << 16;
    u32 hi = u & 0xFFFF0000u;
    u64 r; asm("mov.b64 %0, {%1, %2};" : "=l"(r) : "r"(lo), "r"(hi)); return r;
}
// ---- cp.async helpers ----
__device__ __forceinline__ void cp16(void* sdst, const void* gsrc) {
    u32 s = (u32)__cvta_generic_to_shared(sdst);
    asm volatile("cp.async.cg.shared.global [%0], [%1], 16;" :: "r"(s), "l"(gsrc) : "memory");
}
__device__ __forceinline__ void cp_commit() {
    asm volatile("cp.async.commit_group;" ::: "memory");
}
template<int N>
__device__ __forceinline__ void cp_wait() {
    asm volatile("cp.async.wait_group %0;" :: "n"(N) : "memory");
}

// ---------------- device scratch (no allocation allowed) ----------------
__device__ __align__(16) u32   g_hb [MAXN * (size_t)(HID / 2)]; // bf16x2 GEMM output
__device__ __align__(16) float g_acc[MAXN * (size_t)HID];       // relu'd layer output (f32)
__device__ __align__(16) float2 g_edge[MAXE];                   // {row bits, dis[row]*ew}
__device__ u64   g_degcnt[MAXN];         // (cnt << 44) | (weight sum in 2^-32 units)
__device__ float g_dis [MAXN];
__device__ int   g_off [MAXN + 1];
__device__ int   g_cur [MAXN];
__device__ int   g_bsum[NBMAX];          // flagged block aggregates (0 = not ready)
__device__ int   g_gs  [G_NUM + 1];
__device__ __align__(16) float g_sums[G_NUM * HID];

// ================= GEMM body =================================================
// g_hb[row0..row0+128][HID] = bf16( X[.][K] @ W[K][HID] )
// 3-stage cp.async pipeline, KCH=16, one __syncthreads per chunk.
template<int K, bool SRC_ACC>
__device__ __forceinline__ void gemm_body(const float* __restrict__ X,
                                          const float* __restrict__ W,
                                          int n, int bid) {
    constexpr int KCH = 16;
    constexpr int SXS = KCH + 4;
    constexpr int SWS = HID + 4;
    constexpr int NCH = K / KCH;
    __shared__ float sx[3][128 * SXS];
    __shared__ float sw[3][KCH * SWS];
    const int t = threadIdx.x;
    const int row0 = bid * 128;
    const int hq  = (t & 7) * 8;
    const int hqs = hq + ((t & 7) >> 2) * 4;
    const int rg  = t >> 3;
    const float* xbase = SRC_ACC ? g_acc : X;

    auto stage = [&](int ch, int buf) {
        #pragma unroll
        for (int i = t; i < 128 * (KCH / 4); i += 256) {
            const int r = i >> 2, c = i & 3;
            const int gr = min(row0 + r, n - 1);
            cp16(&sx[buf][r * SXS + c * 4],
                 xbase + (size_t)gr * K + ch * KCH + c * 4);
        }
        {
            const int k = t >> 4, c4 = t & 15;
            cp16(&sw[buf][k * SWS + c4 * 4 + (c4 >= 8 ? 4 : 0)],
                 W + (size_t)(ch * KCH + k) * HID + c4 * 4);
        }
        cp_commit();
    };

    u64 acc[4][4];
    #pragma unroll
    for (int i = 0; i < 4; i++)
        #pragma unroll
        for (int j = 0; j < 4; j++) acc[i][j] = 0;

    stage(0, 0);
    stage(1, 1);
    #pragma unroll
    for (int ch = 0; ch < NCH; ch++) {
        const int buf = ch % 3;
        if (ch + 1 < NCH) cp_wait<1>(); else cp_wait<0>();
        __syncthreads();
        if (ch + 2 < NCH) stage(ch + 2, (ch + 2) % 3);

        #pragma unroll
        for (int qd = 0; qd < KCH / 4; qd++) {
            float4 xr[4];
            #pragma unroll
            for (int i = 0; i < 4; i++)
                xr[i] = *(const float4*)(&sx[buf][(rg + 32 * i) * SXS + qd * 4]);
            #pragma unroll
            for (int kk = 0; kk < 4; kk++) {
                const float* wrow = &sw[buf][(qd * 4 + kk) * SWS];
                const float4 w0 = *(const float4*)(wrow + hqs);
                const float4 w1 = *(const float4*)(wrow + hqs + 4);
                const u64 wp0 = pack2(w0.x, w0.y);
                const u64 wp1 = pack2(w0.z, w0.w);
                const u64 wp2 = pack2(w1.x, w1.y);
                const u64 wp3 = pack2(w1.z, w1.w);
                #pragma unroll
                for (int i = 0; i < 4; i++) {
                    const float xv = ((const float*)&xr[i])[kk];
                    const u64 xp = pack2(xv, xv);
                    acc[i][0] = ffma2(xp, wp0, acc[i][0]);
                    acc[i][1] = ffma2(xp, wp1, acc[i][1]);
                    acc[i][2] = ffma2(xp, wp2, acc[i][2]);
                    acc[i][3] = ffma2(xp, wp3, acc[i][3]);
                }
            }
        }
    }

    #pragma unroll
    for (int i = 0; i < 4; i++) {
        const int gr = row0 + rg + 32 * i;
        if (gr < n) {
            uint4 o;
            float2 f0 = unpack2(acc[i][0]); o.x = cvt_bf16x2(f0.x, f0.y);
            float2 f1 = unpack2(acc[i][1]); o.y = cvt_bf16x2(f1.x, f1.y);
            float2 f2 = unpack2(acc[i][2]); o.z = cvt_bf16x2(f2.x, f2.y);
            float2 f3 = unpack2(acc[i][3]); o.w = cvt_bf16x2(f3.x, f3.y);
            *(uint4*)(g_hb + (size_t)gr * (HID / 2) + (t & 7) * 4) = o;
        }
    }
}

// ---------------- prolog / fused kernels ----------------

// reset + per-graph start offsets (depends only on inputs)
__global__ void k_reset(const int* __restrict__ batch, int n) {
    int i = blockIdx.x * blockDim.x + threadIdx.x;
    if (i < NBMAX) g_bsum[i] = 0;
    if (i >= n) return;
    g_degcnt[i] = 0;
    int b = batch[i];
    int p = (i == 0) ? -1 : batch[i - 1];
    for (int g = p + 1; g <= b; ++g) g_gs[g] = i;
    if (i == n - 1)
        for (int g = b + 1; g <= G_NUM; ++g) g_gs[g] = n;
}

// fused: blocks [0,gB) run GEMM1 rows [0, gB*128); the rest run the degree histogram
__global__ void __launch_bounds__(256) k_deg_gemm1(
    const int* __restrict__ col, const float* __restrict__ ew, int E,
    const float* __restrict__ x, const float* __restrict__ W1, int n, int gB) {
    if ((int)blockIdx.x < gB) {
        gemm_body<IN_DIM, false>(x, W1, n, blockIdx.x);
        return;
    }
    int e = ((int)blockIdx.x - gB) * 256 + threadIdx.x;
    if (e < E) {
        int c = col[e];
        u64 v = (1ull << 44) | (u64)(ew[e] * 4294967296.0f);
        atomicAdd(&g_degcnt[c], v);   // one integer RMW: count + weight sum
    }
}

// single-pass scan: block-local scan + cross-block flagged-aggregate reduce.
// All <=98 blocks are wave-1 resident (98 < 148 SMs) -> spin is safe.
// Produces FINAL g_off (+ sentinel), g_cur, g_dis. No follow-up kernel.
__global__ void k_scan1(int n, int E) {
    __shared__ int s[2][SCAN_B];
    const int t = threadIdx.x;
    const int b = blockIdx.x;
    const int i = b * SCAN_B + t;
    int v = 0;
    if (i < n) {
        u64 dc = g_degcnt[i];
        v = (int)(dc >> 44);
        g_dis[i] = rsqrtf(1.0f + (float)(dc & 0xFFFFFFFFFFFull) * 2.3283064365386963e-10f);
    }
    s[0][t] = v;
    __syncthreads();
    int src = 0;
    #pragma unroll
    for (int d = 1; d < SCAN_B; d <<= 1) {
        int x = s[src][t];
        if (t >= d) x += s[src][t - d];
        s[1 - src][t] = x;
        src = 1 - src;
        __syncthreads();
    }
    const int excl = s[src][t] - v;            // block-local exclusive
    if (t == SCAN_B - 1) {
        // publish flagged inclusive aggregate (flag bit always set; E < 2^30)
        *(volatile int*)&g_bsum[b] = s[src][t] | 0x40000000;
    }
    __syncthreads();

    // cross-block prefix: spin-read aggregates of lower-indexed blocks
    int agg = 0;
    if (t < 128) {
        if (t < b) {
            int r;
            do { r = *(volatile int*)&g_bsum[t]; } while (r == 0);
            agg = r & 0x3FFFFFFF;
        }
        s[0][t] = agg;
    }
    __syncthreads();
    #pragma unroll
    for (int d = 64; d >= 1; d >>= 1) {
        if (t < d) s[0][t] += s[0][t + d];
        __syncthreads();
    }
    const int base = s[0][0];

    if (i < n) {
        const int o = base + excl;
        g_off[i] = o;
        g_cur[i] = o;
    }
    if (b == (int)gridDim.x - 1 && t == SCAN_B - 1) g_off[n] = E;
}

// fused: blocks [0,gB) run GEMM1 rows [rowBase*128, ...); the rest place edges
__global__ void __launch_bounds__(256) k_place_gemm1(
    const int* __restrict__ row, const int* __restrict__ col,
    const float* __restrict__ ew, int E,
    const float* __restrict__ x, const float* __restrict__ W1, int n,
    int gB, int rowBase) {
    if ((int)blockIdx.x < gB) {
        gemm_body<IN_DIM, false>(x, W1, n, rowBase + blockIdx.x);
        return;
    }
    int e = ((int)blockIdx.x - gB) * 256 + threadIdx.x;
    if (e >= E) return;
    int r = row[e];
    int c = col[e];
    float nm = g_dis[r] * ew[e];
    int pos = atomicAdd(&g_cur[c], 1);
    g_edge[pos] = make_float2(__int_as_float(r), nm);
}

// standalone GEMM2
__global__ void __launch_bounds__(256) k_gemm2(const float* __restrict__ W, int n) {
    gemm_body<HID, true>(nullptr, W, n, blockIdx.x);
}

// ---------------- per-node CSR gather (bf16 h), relu applied at store --------
// 8 lanes/node, lane owns 8 cols (one uint4 of bf16x2 per edge = 16B).
// 8-edge unroll for deep MLP; 1-edge tail.
__global__ void k_gather(const float* __restrict__ b, int n) {
    int tid = blockIdx.x * blockDim.x + threadIdx.x;
    int node = tid >> 3;
    if (node >= n) return;
    const int q = tid & 7;

    int e = g_off[node];
    const int e_end = g_off[node + 1];

    u64 a0 = 0, a1 = 0, a2 = 0, a3 = 0;

    for (; e + 7 < e_end; e += 8) {
        float2 r0 = g_edge[e];
        float2 r1 = g_edge[e + 1];
        float2 r2 = g_edge[e + 2];
        float2 r3 = g_edge[e + 3];
        float2 r4 = g_edge[e + 4];
        float2 r5 = g_edge[e + 5];
        float2 r6 = g_edge[e + 6];
        float2 r7 = g_edge[e + 7];
        uint4 h0 = *(const uint4*)(g_hb + (size_t)__float_as_int(r0.x) * (HID / 2) + q * 4);
        uint4 h1 = *(const uint4*)(g_hb + (size_t)__float_as_int(r1.x) * (HID / 2) + q * 4);
        uint4 h2 = *(const uint4*)(g_hb + (size_t)__float_as_int(r2.x) * (HID / 2) + q * 4);
        uint4 h3 = *(const uint4*)(g_hb + (size_t)__float_as_int(r3.x) * (HID / 2) + q * 4);
        uint4 h4 = *(const uint4*)(g_hb + (size_t)__float_as_int(r4.x) * (HID / 2) + q * 4);
        uint4 h5 = *(const uint4*)(g_hb + (size_t)__float_as_int(r5.x) * (HID / 2) + q * 4);
        uint4 h6 = *(const uint4*)(g_hb + (size_t)__float_as_int(r6.x) * (HID / 2) + q * 4);
        uint4 h7 = *(const uint4*)(g_hb + (size_t)__float_as_int(r7.x) * (HID / 2) + q * 4);
        u64 nm;
        nm = pack2(r0.y, r0.y);
        a0 = ffma2(nm, bf2f2(h0.x), a0); a1 = ffma2(nm, bf2f2(h0.y), a1);
        a2 = ffma2(nm, bf2f2(h0.z), a2); a3 = ffma2(nm, bf2f2(h0.w), a3);
        nm = pack2(r1.y, r1.y);
        a0 = ffma2(nm, bf2f2(h1.x), a0); a1 = ffma2(nm, bf2f2(h1.y), a1);
        a2 = ffma2(nm, bf2f2(h1.z), a2); a3 = ffma2(nm, bf2f2(h1.w), a3);
        nm = pack2(r2.y, r2.y);
        a0 = ffma2(nm, bf2f2(h2.x), a0); a1 = ffma2(nm, bf2f2(h2.y), a1);
        a2 = ffma2(nm, bf2f2(h2.z), a2); a3 = ffma2(nm, bf2f2(h2.w), a3);
        nm = pack2(r3.y, r3.y);
        a0 = ffma2(nm, bf2f2(h3.x), a0); a1 = ffma2(nm, bf2f2(h3.y), a1);
        a2 = ffma2(nm, bf2f2(h3.z), a2); a3 = ffma2(nm, bf2f2(h3.w), a3);
        nm = pack2(r4.y, r4.y);
        a0 = ffma2(nm, bf2f2(h4.x), a0); a1 = ffma2(nm, bf2f2(h4.y), a1);
        a2 = ffma2(nm, bf2f2(h4.z), a2); a3 = ffma2(nm, bf2f2(h4.w), a3);
        nm = pack2(r5.y, r5.y);
        a0 = ffma2(nm, bf2f2(h5.x), a0); a1 = ffma2(nm, bf2f2(h5.y), a1);
        a2 = ffma2(nm, bf2f2(h5.z), a2); a3 = ffma2(nm, bf2f2(h5.w), a3);
        nm = pack2(r6.y, r6.y);
        a0 = ffma2(nm, bf2f2(h6.x), a0); a1 = ffma2(nm, bf2f2(h6.y), a1);
        a2 = ffma2(nm, bf2f2(h6.z), a2); a3 = ffma2(nm, bf2f2(h6.w), a3);
        nm = pack2(r7.y, r7.y);
        a0 = ffma2(nm, bf2f2(h7.x), a0); a1 = ffma2(nm, bf2f2(h7.y), a1);
        a2 = ffma2(nm, bf2f2(h7.z), a2); a3 = ffma2(nm, bf2f2(h7.w), a3);
    }
    for (; e < e_end; e++) {
        float2 r0 = g_edge[e];
        uint4 h0 = *(const uint4*)(g_hb + (size_t)__float_as_int(r0.x) * (HID / 2) + q * 4);
        const u64 n0 = pack2(r0.y, r0.y);
        a0 = ffma2(n0, bf2f2(h0.x), a0); a1 = ffma2(n0, bf2f2(h0.y), a1);
        a2 = ffma2(n0, bf2f2(h0.z), a2); a3 = ffma2(n0, bf2f2(h0.w), a3);
    }

    const float d  = g_dis[node];
    const float dd = d * d;
    const uint4 hs = *(const uint4*)(g_hb + (size_t)node * (HID / 2) + q * 4);
    const float* bb = b + q * 8;
    float out[8];
    u64 aa[4] = {a0, a1, a2, a3};
    u32 hh[4] = {hs.x, hs.y, hs.z, hs.w};
    #pragma unroll
    for (int j = 0; j < 4; j++) {
        float2 s = unpack2(bf2f2(hh[j]));
        float2 ev = unpack2(aa[j]);
        out[2*j]   = fmaxf(bb[2*j]   + dd * s.x + d * ev.x, 0.0f);
        out[2*j+1] = fmaxf(bb[2*j+1] + dd * s.y + d * ev.y, 0.0f);
    }
    float* dst = g_acc + (size_t)node * HID + q * 8;
    *(float4*)(dst)     = make_float4(out[0], out[1], out[2], out[3]);
    *(float4*)(dst + 4) = make_float4(out[4], out[5], out[6], out[7]);
}

// ---------------- pool + head (g_acc already relu'd) ----------------
__global__ void k_pool(int n) {
    const int g = blockIdx.x;
    const int t = threadIdx.x;
    const int q = t & 15;
    const int sub = t >> 4;
    const int s = g_gs[g], e = g_gs[g + 1];

    float4 acc = make_float4(0.f, 0.f, 0.f, 0.f);
    for (int i = s + sub; i < e; i += 16) {
        float4 v = ((const float4*)(g_acc + (size_t)i * HID))[q];
        acc.x += v.x; acc.y += v.y; acc.z += v.z; acc.w += v.w;
    }
    __shared__ float4 sm[256];
    sm[t] = acc;
    __syncthreads();
    if (sub == 0) {
        float4 a = acc;
        #pragma unroll
        for (int k = 1; k < 16; k++) {
            float4 bb = sm[k * 16 + q];
            a.x += bb.x; a.y += bb.y; a.z += bb.z; a.w += bb.w;
        }
        ((float4*)(g_sums + g * HID))[q] = a;
    }
}

__global__ void k_final(const float* __restrict__ Wc,
                        const float* __restrict__ bc,
                        float* __restrict__ out) {
    int g = blockIdx.x * blockDim.x + threadIdx.x;
    if (g >= G_NUM) return;
    const float c = fmaxf((float)(g_gs[g + 1] - g_gs[g]), 1.0f);
    float acc = 0.0f;
    #pragma unroll
    for (int h = 0; h < HID; h++)
        acc += g_sums[g * HID + h] * Wc[h];
    out[g] = acc / c + bc[0];
}

// ---------------- launcher ----------------
extern "C" void kernel_launch(void* const* d_in, const int* in_sizes, int n_in,
                              void* d_out, int out_size) {
    const float* x     = (const float*)d_in[0];
    const int*   ei    = (const int*)  d_in[1];   // int32 (JAX x64 disabled)
    const float* ew    = (const float*)d_in[2];
    const int*   batch = (const int*)  d_in[3];
    const float* W1    = (const float*)d_in[4];
    const float* b1    = (const float*)d_in[5];
    const float* W2    = (const float*)d_in[6];
    const float* b2    = (const float*)d_in[7];
    const float* Wc    = (const float*)d_in[8];
    const float* bc    = (const float*)d_in[9];
    float* out = (float*)d_out;

    const int n = in_sizes[0] / IN_DIM;   // 100000
    const int E = in_sizes[2];            // 3200000
    const int* row = ei;
    const int* col = ei + E;
    const int T = 256;
    const int nb = (n + SCAN_B - 1) / SCAN_B;     // 98 blocks (single wave)
    const int nblk  = (n + 127) / 128;
    const int half1 = (nblk + 1) / 2;
    const int half2 = nblk - half1;
    const int eblk  = (E + T - 1) / T;

    k_reset<<<(n + T - 1) / T, T>>>(batch, n);
    // GEMM1 (first half) overlapped with packed degree histogram
    k_deg_gemm1<<<half1 + eblk, T>>>(col, ew, E, x, W1, n, half1);
    k_scan1<<<nb, SCAN_B>>>(n, E);                // final offsets, one pass
    // GEMM1 (second half) overlapped with edge placement
    k_place_gemm1<<<half2 + eblk, T>>>(row, col, ew, E, x, W1, n, half2, half1);

    k_gather<<<(n * 8 + T - 1) / T, T>>>(b1, n);  // layer 1 -> g_acc

    k_gemm2<<<nblk, T>>>(W2, n);                  // layer 2 GEMM
    k_gather<<<(n * 8 + T - 1) / T, T>>>(b2, n);  // layer 2 -> g_acc

    k_pool <<<G_NUM, 256>>>(n);
    k_final<<<1, T>>>(Wc, bc, out);
}

// round 16
// speedup vs baseline: 1.1465x; 1.0480x over previous
#include <cuda_runtime.h>

#define MAXN   100000
#define MAXE   3200000
#define IN_DIM 128
#define HID    64
#define G_NUM  256
#define SCAN_B 1024
#define NBMAX  ((MAXN + SCAN_B - 1) / SCAN_B)

typedef unsigned long long u64;
typedef unsigned int u32;

// ---- packed fp32x2 helpers (sm_100+) ----
__device__ __forceinline__ u64 pack2(float lo, float hi) {
    u64 r; asm("mov.b64 %0, {%1, %2};" : "=l"(r) : "f"(lo), "f"(hi)); return r;
}
__device__ __forceinline__ u64 ffma2(u64 a, u64 b, u64 c) {
    u64 d; asm("fma.rn.f32x2 %0, %1, %2, %3;" : "=l"(d) : "l"(a), "l"(b), "l"(c)); return d;
}
__device__ __forceinline__ float2 unpack2(u64 v) {
    float2 f; asm("mov.b64 {%0, %1}, %2;" : "=f"(f.x), "=f"(f.y) : "l"(v)); return f;
}
__device__ __forceinline__ u32 cvt_bf16x2(float lo, float hi) {
    u32 r; asm("cvt.rn.bf16x2.f32 %0, %1, %2;" : "=r"(r) : "f"(hi), "f"(lo)); return r;
}
__device__ __forceinline__ u64 bf2f2(u32 u) {
    u32 lo = u << 16;
    u32 hi = u & 0xFFFF0000u;
    u64 r; asm("mov.b64 %0, {%1, %2};" : "=l"(r) : "r"(lo), "r"(hi)); return r;
}
// ---- cp.async helpers ----
__device__ __forceinline__ void cp16(void* sdst, const void* gsrc) {
    u32 s = (u32)__cvta_generic_to_shared(sdst);
    asm volatile("cp.async.cg.shared.global [%0], [%1], 16;" :: "r"(s), "l"(gsrc) : "memory");
}
__device__ __forceinline__ void cp_commit() {
    asm volatile("cp.async.commit_group;" ::: "memory");
}
template<int N>
__device__ __forceinline__ void cp_wait() {
    asm volatile("cp.async.wait_group %0;" :: "n"(N) : "memory");
}

// ---------------- device scratch (no allocation allowed) ----------------
__device__ __align__(16) u32   g_hb [MAXN * (size_t)(HID / 2)]; // bf16x2 GEMM output
__device__ __align__(16) float g_acc[MAXN * (size_t)HID];       // relu'd layer output (f32)
__device__ __align__(16) float2 g_edge[MAXE];                   // {row bits, dis[row]*ew}
__device__ __align__(16) u32   g_rank[MAXE];                    // per-edge rank within dest
__device__ u64   g_degcnt[MAXN];         // (cnt << 44) | (weight sum in 2^-32 units)
__device__ float g_dis [MAXN];
__device__ int   g_off [MAXN + 1];
__device__ int   g_bsum[NBMAX];          // flagged block aggregates (0 = not ready)
__device__ int   g_gs  [G_NUM + 1];
__device__ __align__(16) float g_sums[G_NUM * HID];

// ================= GEMM body =================================================
// g_hb[row0..row0+128][HID] = bf16( X[.][K] @ W[K][HID] )
// 3-stage cp.async pipeline, KCH=16, one __syncthreads per chunk.
template<int K, bool SRC_ACC>
__device__ __forceinline__ void gemm_body(const float* __restrict__ X,
                                          const float* __restrict__ W,
                                          int n, int bid) {
    constexpr int KCH = 16;
    constexpr int SXS = KCH + 4;
    constexpr int SWS = HID + 4;
    constexpr int NCH = K / KCH;
    __shared__ float sx[3][128 * SXS];
    __shared__ float sw[3][KCH * SWS];
    const int t = threadIdx.x;
    const int row0 = bid * 128;
    const int hq  = (t & 7) * 8;
    const int hqs = hq + ((t & 7) >> 2) * 4;
    const int rg  = t >> 3;
    const float* xbase = SRC_ACC ? g_acc : X;

    auto stage = [&](int ch, int buf) {
        #pragma unroll
        for (int i = t; i < 128 * (KCH / 4); i += 256) {
            const int r = i >> 2, c = i & 3;
            const int gr = min(row0 + r, n - 1);
            cp16(&sx[buf][r * SXS + c * 4],
                 xbase + (size_t)gr * K + ch * KCH + c * 4);
        }
        {
            const int k = t >> 4, c4 = t & 15;
            cp16(&sw[buf][k * SWS + c4 * 4 + (c4 >= 8 ? 4 : 0)],
                 W + (size_t)(ch * KCH + k) * HID + c4 * 4);
        }
        cp_commit();
    };

    u64 acc[4][4];
    #pragma unroll
    for (int i = 0; i < 4; i++)
        #pragma unroll
        for (int j = 0; j < 4; j++) acc[i][j] = 0;

    stage(0, 0);
    stage(1, 1);
    #pragma unroll
    for (int ch = 0; ch < NCH; ch++) {
        const int buf = ch % 3;
        if (ch + 1 < NCH) cp_wait<1>(); else cp_wait<0>();
        __syncthreads();
        if (ch + 2 < NCH) stage(ch + 2, (ch + 2) % 3);

        #pragma unroll
        for (int qd = 0; qd < KCH / 4; qd++) {
            float4 xr[4];
            #pragma unroll
            for (int i = 0; i < 4; i++)
                xr[i] = *(const float4*)(&sx[buf][(rg + 32 * i) * SXS + qd * 4]);
            #pragma unroll
            for (int kk = 0; kk < 4; kk++) {
                const float* wrow = &sw[buf][(qd * 4 + kk) * SWS];
                const float4 w0 = *(const float4*)(wrow + hqs);
                const float4 w1 = *(const float4*)(wrow + hqs + 4);
                const u64 wp0 = pack2(w0.x, w0.y);
                const u64 wp1 = pack2(w0.z, w0.w);
                const u64 wp2 = pack2(w1.x, w1.y);
                const u64 wp3 = pack2(w1.z, w1.w);
                #pragma unroll
                for (int i = 0; i < 4; i++) {
                    const float xv = ((const float*)&xr[i])[kk];
                    const u64 xp = pack2(xv, xv);
                    acc[i][0] = ffma2(xp, wp0, acc[i][0]);
                    acc[i][1] = ffma2(xp, wp1, acc[i][1]);
                    acc[i][2] = ffma2(xp, wp2, acc[i][2]);
                    acc[i][3] = ffma2(xp, wp3, acc[i][3]);
                }
            }
        }
    }

    #pragma unroll
    for (int i = 0; i < 4; i++) {
        const int gr = row0 + rg + 32 * i;
        if (gr < n) {
            uint4 o;
            float2 f0 = unpack2(acc[i][0]); o.x = cvt_bf16x2(f0.x, f0.y);
            float2 f1 = unpack2(acc[i][1]); o.y = cvt_bf16x2(f1.x, f1.y);
            float2 f2 = unpack2(acc[i][2]); o.z = cvt_bf16x2(f2.x, f2.y);
            float2 f3 = unpack2(acc[i][3]); o.w = cvt_bf16x2(f3.x, f3.y);
            *(uint4*)(g_hb + (size_t)gr * (HID / 2) + (t & 7) * 4) = o;
        }
    }
}

// ---------------- prolog / fused kernels ----------------

// reset + per-graph start offsets (depends only on inputs)
__global__ void k_reset(const int* __restrict__ batch, int n) {
    int i = blockIdx.x * blockDim.x + threadIdx.x;
    if (i < NBMAX) g_bsum[i] = 0;
    if (i >= n) return;
    g_degcnt[i] = 0;
    int b = batch[i];
    int p = (i == 0) ? -1 : batch[i - 1];
    for (int g = p + 1; g <= b; ++g) g_gs[g] = i;
    if (i == n - 1)
        for (int g = b + 1; g <= G_NUM; ++g) g_gs[g] = n;
}

// fused: blocks [0,gB) run GEMM1 rows [0, gB*128); the rest run the degree
// histogram, 4 edges/thread, capturing each edge's rank from the atomic return.
__global__ void __launch_bounds__(256) k_deg_gemm1(
    const int* __restrict__ col, const float* __restrict__ ew, int E,
    const float* __restrict__ x, const float* __restrict__ W1, int n, int gB) {
    if ((int)blockIdx.x < gB) {
        gemm_body<IN_DIM, false>(x, W1, n, blockIdx.x);
        return;
    }
    const int base = ((int)blockIdx.x - gB) * 1024 + threadIdx.x * 4;
    if (base + 3 < E) {
        int4   c4 = *(const int4*)(col + base);
        float4 w4 = *(const float4*)(ew + base);
        uint4 r4;
        r4.x = (u32)(atomicAdd(&g_degcnt[c4.x], (1ull << 44) | (u64)(w4.x * 4294967296.0f)) >> 44);
        r4.y = (u32)(atomicAdd(&g_degcnt[c4.y], (1ull << 44) | (u64)(w4.y * 4294967296.0f)) >> 44);
        r4.z = (u32)(atomicAdd(&g_degcnt[c4.z], (1ull << 44) | (u64)(w4.z * 4294967296.0f)) >> 44);
        r4.w = (u32)(atomicAdd(&g_degcnt[c4.w], (1ull << 44) | (u64)(w4.w * 4294967296.0f)) >> 44);
        *(uint4*)(g_rank + base) = r4;
    } else {
        for (int e = base; e < E; e++) {
            int c = col[e];
            u64 v = (1ull << 44) | (u64)(ew[e] * 4294967296.0f);
            g_rank[e] = (u32)(atomicAdd(&g_degcnt[c], v) >> 44);
        }
    }
}

// single-pass scan: block-local scan + cross-block flagged-aggregate reduce.
// All <=98 blocks are wave-1 resident (98 < 148 SMs) -> spin is safe.
// Produces FINAL g_off (+ sentinel), g_dis. No follow-up kernel.
__global__ void k_scan1(int n, int E) {
    __shared__ int s[2][SCAN_B];
    const int t = threadIdx.x;
    const int b = blockIdx.x;
    const int i = b * SCAN_B + t;
    int v = 0;
    if (i < n) {
        u64 dc = g_degcnt[i];
        v = (int)(dc >> 44);
        g_dis[i] = rsqrtf(1.0f + (float)(dc & 0xFFFFFFFFFFFull) * 2.3283064365386963e-10f);
    }
    s[0][t] = v;
    __syncthreads();
    int src = 0;
    #pragma unroll
    for (int d = 1; d < SCAN_B; d <<= 1) {
        int x = s[src][t];
        if (t >= d) x += s[src][t - d];
        s[1 - src][t] = x;
        src = 1 - src;
        __syncthreads();
    }
    const int excl = s[src][t] - v;            // block-local exclusive
    if (t == SCAN_B - 1) {
        *(volatile int*)&g_bsum[b] = s[src][t] | 0x40000000;
    }
    __syncthreads();

    int agg = 0;
    if (t < 128) {
        if (t < b) {
            int r;
            do { r = *(volatile int*)&g_bsum[t]; } while (r == 0);
            agg = r & 0x3FFFFFFF;
        }
        s[0][t] = agg;
    }
    __syncthreads();
    #pragma unroll
    for (int d = 64; d >= 1; d >>= 1) {
        if (t < d) s[0][t] += s[0][t + d];
        __syncthreads();
    }
    const int base = s[0][0];

    if (i < n) g_off[i] = base + excl;
    if (b == (int)gridDim.x - 1 && t == SCAN_B - 1) g_off[n] = E;
}

// fused: blocks [0,gB) run GEMM1 rows [rowBase*128, ...); the rest place edges
// WITHOUT atomics: slot = g_off[col] + rank. 4 edges/thread.
__global__ void __launch_bounds__(256) k_place_gemm1(
    const int* __restrict__ row, const int* __restrict__ col,
    const float* __restrict__ ew, int E,
    const float* __restrict__ x, const float* __restrict__ W1, int n,
    int gB, int rowBase) {
    if ((int)blockIdx.x < gB) {
        gemm_body<IN_DIM, false>(x, W1, n, rowBase + blockIdx.x);
        return;
    }
    const int base = ((int)blockIdx.x - gB) * 1024 + threadIdx.x * 4;
    if (base + 3 < E) {
        int4   r4 = *(const int4*)(row + base);
        int4   c4 = *(const int4*)(col + base);
        float4 w4 = *(const float4*)(ew + base);
        uint4  k4 = *(const uint4*)(g_rank + base);
        float dA = g_dis[r4.x], dB = g_dis[r4.y], dC = g_dis[r4.z], dD = g_dis[r4.w];
        int   oA = g_off[c4.x], oB = g_off[c4.y], oC = g_off[c4.z], oD = g_off[c4.w];
        g_edge[oA + k4.x] = make_float2(__int_as_float(r4.x), dA * w4.x);
        g_edge[oB + k4.y] = make_float2(__int_as_float(r4.y), dB * w4.y);
        g_edge[oC + k4.z] = make_float2(__int_as_float(r4.z), dC * w4.z);
        g_edge[oD + k4.w] = make_float2(__int_as_float(r4.w), dD * w4.w);
    } else {
        for (int e = base; e < E; e++) {
            int r = row[e], c = col[e];
            g_edge[g_off[c] + g_rank[e]] =
                make_float2(__int_as_float(r), g_dis[r] * ew[e]);
        }
    }
}

// standalone GEMM2
__global__ void __launch_bounds__(256) k_gemm2(const float* __restrict__ W, int n) {
    gemm_body<HID, true>(nullptr, W, n, blockIdx.x);
}

// ---------------- per-node CSR gather (bf16 h), relu applied at store --------
// 8 lanes/node, lane owns 8 cols (one uint4 of bf16x2 per edge = 16B).
// 8-edge unroll for deep MLP; 1-edge tail.
__global__ void k_gather(const float* __restrict__ b, int n) {
    int tid = blockIdx.x * blockDim.x + threadIdx.x;
    int node = tid >> 3;
    if (node >= n) return;
    const int q = tid & 7;

    int e = g_off[node];
    const int e_end = g_off[node + 1];

    u64 a0 = 0, a1 = 0, a2 = 0, a3 = 0;

    for (; e + 7 < e_end; e += 8) {
        float2 r0 = g_edge[e];
        float2 r1 = g_edge[e + 1];
        float2 r2 = g_edge[e + 2];
        float2 r3 = g_edge[e + 3];
        float2 r4 = g_edge[e + 4];
        float2 r5 = g_edge[e + 5];
        float2 r6 = g_edge[e + 6];
        float2 r7 = g_edge[e + 7];
        uint4 h0 = *(const uint4*)(g_hb + (size_t)__float_as_int(r0.x) * (HID / 2) + q * 4);
        uint4 h1 = *(const uint4*)(g_hb + (size_t)__float_as_int(r1.x) * (HID / 2) + q * 4);
        uint4 h2 = *(const uint4*)(g_hb + (size_t)__float_as_int(r2.x) * (HID / 2) + q * 4);
        uint4 h3 = *(const uint4*)(g_hb + (size_t)__float_as_int(r3.x) * (HID / 2) + q * 4);
        uint4 h4 = *(const uint4*)(g_hb + (size_t)__float_as_int(r4.x) * (HID / 2) + q * 4);
        uint4 h5 = *(const uint4*)(g_hb + (size_t)__float_as_int(r5.x) * (HID / 2) + q * 4);
        uint4 h6 = *(const uint4*)(g_hb + (size_t)__float_as_int(r6.x) * (HID / 2) + q * 4);
        uint4 h7 = *(const uint4*)(g_hb + (size_t)__float_as_int(r7.x) * (HID / 2) + q * 4);
        u64 nm;
        nm = pack2(r0.y, r0.y);
        a0 = ffma2(nm, bf2f2(h0.x), a0); a1 = ffma2(nm, bf2f2(h0.y), a1);
        a2 = ffma2(nm, bf2f2(h0.z), a2); a3 = ffma2(nm, bf2f2(h0.w), a3);
        nm = pack2(r1.y, r1.y);
        a0 = ffma2(nm, bf2f2(h1.x), a0); a1 = ffma2(nm, bf2f2(h1.y), a1);
        a2 = ffma2(nm, bf2f2(h1.z), a2); a3 = ffma2(nm, bf2f2(h1.w), a3);
        nm = pack2(r2.y, r2.y);
        a0 = ffma2(nm, bf2f2(h2.x), a0); a1 = ffma2(nm, bf2f2(h2.y), a1);
        a2 = ffma2(nm, bf2f2(h2.z), a2); a3 = ffma2(nm, bf2f2(h2.w), a3);
        nm = pack2(r3.y, r3.y);
        a0 = ffma2(nm, bf2f2(h3.x), a0); a1 = ffma2(nm, bf2f2(h3.y), a1);
        a2 = ffma2(nm, bf2f2(h3.z), a2); a3 = ffma2(nm, bf2f2(h3.w), a3);
        nm = pack2(r4.y, r4.y);
        a0 = ffma2(nm, bf2f2(h4.x), a0); a1 = ffma2(nm, bf2f2(h4.y), a1);
        a2 = ffma2(nm, bf2f2(h4.z), a2); a3 = ffma2(nm, bf2f2(h4.w), a3);
        nm = pack2(r5.y, r5.y);
        a0 = ffma2(nm, bf2f2(h5.x), a0); a1 = ffma2(nm, bf2f2(h5.y), a1);
        a2 = ffma2(nm, bf2f2(h5.z), a2); a3 = ffma2(nm, bf2f2(h5.w), a3);
        nm = pack2(r6.y, r6.y);
        a0 = ffma2(nm, bf2f2(h6.x), a0); a1 = ffma2(nm, bf2f2(h6.y), a1);
        a2 = ffma2(nm, bf2f2(h6.z), a2); a3 = ffma2(nm, bf2f2(h6.w), a3);
        nm = pack2(r7.y, r7.y);
        a0 = ffma2(nm, bf2f2(h7.x), a0); a1 = ffma2(nm, bf2f2(h7.y), a1);
        a2 = ffma2(nm, bf2f2(h7.z), a2); a3 = ffma2(nm, bf2f2(h7.w), a3);
    }
    for (; e < e_end; e++) {
        float2 r0 = g_edge[e];
        uint4 h0 = *(const uint4*)(g_hb + (size_t)__float_as_int(r0.x) * (HID / 2) + q * 4);
        const u64 n0 = pack2(r0.y, r0.y);
        a0 = ffma2(n0, bf2f2(h0.x), a0); a1 = ffma2(n0, bf2f2(h0.y), a1);
        a2 = ffma2(n0, bf2f2(h0.z), a2); a3 = ffma2(n0, bf2f2(h0.w), a3);
    }

    const float d  = g_dis[node];
    const float dd = d * d;
    const uint4 hs = *(const uint4*)(g_hb + (size_t)node * (HID / 2) + q * 4);
    const float* bb = b + q * 8;
    float out[8];
    u64 aa[4] = {a0, a1, a2, a3};
    u32 hh[4] = {hs.x, hs.y, hs.z, hs.w};
    #pragma unroll
    for (int j = 0; j < 4; j++) {
        float2 s = unpack2(bf2f2(hh[j]));
        float2 ev = unpack2(aa[j]);
        out[2*j]   = fmaxf(bb[2*j]   + dd * s.x + d * ev.x, 0.0f);
        out[2*j+1] = fmaxf(bb[2*j+1] + dd * s.y + d * ev.y, 0.0f);
    }
    float* dst = g_acc + (size_t)node * HID + q * 8;
    *(float4*)(dst)     = make_float4(out[0], out[1], out[2], out[3]);
    *(float4*)(dst + 4) = make_float4(out[4], out[5], out[6], out[7]);
}

// ---------------- pool + head (g_acc already relu'd) ----------------
__global__ void k_pool(int n) {
    const int g = blockIdx.x;
    const int t = threadIdx.x;
    const int q = t & 15;
    const int sub = t >> 4;
    const int s = g_gs[g], e = g_gs[g + 1];

    float4 acc = make_float4(0.f, 0.f, 0.f, 0.f);
    for (int i = s + sub; i < e; i += 16) {
        float4 v = ((const float4*)(g_acc + (size_t)i * HID))[q];
        acc.x += v.x; acc.y += v.y; acc.z += v.z; acc.w += v.w;
    }
    __shared__ float4 sm[256];
    sm[t] = acc;
    __syncthreads();
    if (sub == 0) {
        float4 a = acc;
        #pragma unroll
        for (int k = 1; k < 16; k++) {
            float4 bb = sm[k * 16 + q];
            a.x += bb.x; a.y += bb.y; a.z += bb.z; a.w += bb.w;
        }
        ((float4*)(g_sums + g * HID))[q] = a;
    }
}

__global__ void k_final(const float* __restrict__ Wc,
                        const float* __restrict__ bc,
                        float* __restrict__ out) {
    int g = blockIdx.x * blockDim.x + threadIdx.x;
    if (g >= G_NUM) return;
    const float c = fmaxf((float)(g_gs[g + 1] - g_gs[g]), 1.0f);
    float acc = 0.0f;
    #pragma unroll
    for (int h = 0; h < HID; h++)
        acc += g_sums[g * HID + h] * Wc[h];
    out[g] = acc / c + bc[0];
}

// ---------------- launcher ----------------
extern "C" void kernel_launch(void* const* d_in, const int* in_sizes, int n_in,
                              void* d_out, int out_size) {
    const float* x     = (const float*)d_in[0];
    const int*   ei    = (const int*)  d_in[1];   // int32 (JAX x64 disabled)
    const float* ew    = (const float*)d_in[2];
    const int*   batch = (const int*)  d_in[3];
    const float* W1    = (const float*)d_in[4];
    const float* b1    = (const float*)d_in[5];
    const float* W2    = (const float*)d_in[6];
    const float* b2    = (const float*)d_in[7];
    const float* Wc    = (const float*)d_in[8];
    const float* bc    = (const float*)d_in[9];
    float* out = (float*)d_out;

    const int n = in_sizes[0] / IN_DIM;   // 100000
    const int E = in_sizes[2];            // 3200000
    const int* row = ei;
    const int* col = ei + E;
    const int T = 256;
    const int nb = (n + SCAN_B - 1) / SCAN_B;     // 98 blocks (single wave)
    const int nblk  = (n + 127) / 128;
    const int half1 = (nblk + 1) / 2;
    const int half2 = nblk - half1;
    const int eblk  = (E + 1023) / 1024;          // 4 edges/thread

    k_reset<<<(n + T - 1) / T, T>>>(batch, n);
    // GEMM1 (first half) overlapped with packed degree histogram (+rank capture)
    k_deg_gemm1<<<half1 + eblk, T>>>(col, ew, E, x, W1, n, half1);
    k_scan1<<<nb, SCAN_B>>>(n, E);                // final offsets, one pass
    // GEMM1 (second half) overlapped with atomic-free edge placement
    k_place_gemm1<<<half2 + eblk, T>>>(row, col, ew, E, x, W1, n, half2, half1);

    k_gather<<<(n * 8 + T - 1) / T, T>>>(b1, n);  // layer 1 -> g_acc

    k_gemm2<<<nblk, T>>>(W2, n);                  // layer 2 GEMM
    k_gather<<<(n * 8 + T - 1) / T, T>>>(b2, n);  // layer 2 -> g_acc

    k_pool <<<G_NUM, 256>>>(n);
    k_final<<<1, T>>>(Wc, bc, out);
}